// round 5
// baseline (speedup 1.0000x reference)
#include <cuda_runtime.h>
#include <cuda_bf16.h>

// Erosion (min filter) k=18, SAME (pad_lo=8, pad_hi=9), on y = x*0.5+0.5.
// NCHW (32,3,512,512) fp32 = 96 planes of 512x512.
//
// Horizontal-first fused separable min filter (R4 structure, retiled):
//  Phase A: warp-per-row, lane owns 4 contiguous cols (float4): coalesced
//    LDG.128 + STS.128; 18-wide window built from per-lane prefix/suffix mins
//    via 10 wrap-shuffles per 128-col round. 81 h-min rows (TY+17) -> smem.
//  Phase B: thread-per-(column, half-strip). Taps 16..32 (shared by both
//    16-row van Herk chunks) hoisted into 17 registers -> 49 LDS instead of
//    66 per 32 outputs. Coalesced STG.32 (streaming .cs hint).
//  TY=64, 1024 threads, 166KB smem, one barrier.

#define W 512
#define H 512
#define TY 64
#define HROWS (TY + 17)            // 81 horizontal-result rows
#define NTHREADS 1024
#define SMEM_BYTES (HROWS * W * 4) // 165,888 B

__global__ __launch_bounds__(NTHREADS, 1)
void erode18_kernel(const float* __restrict__ x, float* __restrict__ out) {
    extern __shared__ float s_h[];  // [HROWS][W]

    const int tid  = threadIdx.x;
    const int lane = tid & 31;
    const int warp = tid >> 5;          // 0..31
    const int rowBase = blockIdx.x * TY;
    const long plane = (long)blockIdx.y * (W * H);
    const float INF = __int_as_float(0x7f800000);
    const unsigned FULL = 0xFFFFFFFFu;

    // ================= Phase A: horizontal min-18, warp-per-row =================
    for (int r = warp; r < HROWS; r += 32) {
        const int gr = rowBase - 8 + r;
        const bool inb = (unsigned)gr < (unsigned)H;
        const float4* rowp = (const float4*)(x + plane + (long)gr * W);

        float4 v = inb ? __ldg(rowp + lane)
                       : make_float4(INF, INF, INF, INF);
        // prev-round carries (cols < 0 are +inf for round 0)
        float pS0 = INF, pS1 = INF, pS2 = INF, pS3 = INF, pF = INF;

        float4* orow = (float4*)(s_h + r * W);

        #pragma unroll
        for (int j = 0; j < 4; ++j) {
            float4 vn = (j < 3 && inb) ? __ldg(rowp + 32 * (j + 1) + lane)
                                       : make_float4(INF, INF, INF, INF);
            // own prefix/suffix mins over v (taps = 4 cols)
            float P1 = fminf(v.x, v.y);
            float P2 = fminf(P1, v.z);
            float F  = fminf(P2, v.w);           // full min
            float S2 = fminf(v.z, v.w);
            float S1 = fminf(v.y, S2);
            // next-round prefixes
            float Pn1 = fminf(vn.x, vn.y);
            float Pn2 = fminf(Pn1, vn.z);
            float Fn  = fminf(Pn2, vn.w);

            // src = lane-2 (wrap); wrap sources 30,31 export prev-round values
            float eS0 = (lane >= 30) ? pS0 : F;
            float eS1 = (lane >= 30) ? pS1 : S1;
            float eS2 = (lane >= 30) ? pS2 : S2;
            float eS3 = (lane >= 30) ? pS3 : v.w;
            float u0 = __shfl_sync(FULL, eS0, (lane + 30) & 31);
            float u1 = __shfl_sync(FULL, eS1, (lane + 30) & 31);
            float u2 = __shfl_sync(FULL, eS2, (lane + 30) & 31);
            float u3 = __shfl_sync(FULL, eS3, (lane + 30) & 31);
            // F from lane-1 (wrap source 31 exports prev round)
            float eFu = (lane == 31) ? pF : F;
            float fu = __shfl_sync(FULL, eFu, (lane + 31) & 31);
            // F from lane+1 (wrap source 0 exports next round)
            float eFd = (lane == 0) ? Fn : F;
            float fd = __shfl_sync(FULL, eFd, (lane + 1) & 31);
            // prefixes from lane+2 (wrap sources 0,1 export next round)
            float eP1 = (lane <= 1) ? Pn1 : P1;
            float eP2 = (lane <= 1) ? Pn2 : P2;
            float eP3 = (lane <= 1) ? Fn  : F;
            float d1 = __shfl_sync(FULL, eP1, (lane + 2) & 31);
            float d2 = __shfl_sync(FULL, eP2, (lane + 2) & 31);
            float d3 = __shfl_sync(FULL, eP3, (lane + 2) & 31);
            // v.x from lane+3 (wrap sources 0..2 export next round)
            float evx = (lane <= 2) ? vn.x : v.x;
            float dx = __shfl_sync(FULL, evx, (lane + 3) & 31);

            float core = fminf(fminf(fu, F), fd);   // lanes l-1, l, l+1
            float4 ov;
            ov.x = fminf(fminf(u0, core), d1);      // window [-8, +9]
            ov.y = fminf(fminf(u1, core), d2);
            ov.z = fminf(fminf(u2, core), d3);
            ov.w = fminf(fminf(u3, core), fminf(d3, dx));
            orow[32 * j + lane] = ov;

            pS0 = F; pS1 = S1; pS2 = S2; pS3 = v.w; pF = F;
            v = vn;
        }
    }
    __syncthreads();

    // ============== Phase B: vertical min-18, thread-per-(col, half) ==============
    {
        const int g = tid >> 9;          // half-strip 0/1 -> rows g*32 .. g*32+31
        const int c = tid & 511;         // column
        const float* cp = s_h + (g * 32) * W + c;   // tap row 0 (rel)
        float* op = out + plane + (long)(rowBase + g * 32) * W + c;

        // shared taps 16..32 (used by both 16-row chunks), loaded once
        float t[17];
        #pragma unroll
        for (int i = 0; i < 17; ++i) t[i] = cp[(16 + i) * W];

        float S[16];

        // chunk A: output rows 0..15, taps 0..32
        {
            float s = t[1];                       // tap 17
            #pragma unroll
            for (int i = 16; i >= 0; --i) {       // taps 16..0
                s = fminf(s, (i == 16) ? t[0] : cp[i * W]);
                if (i <= 15) S[i] = s;
            }
        }
        __stcs(op, fmaf(S[0], 0.5f, 0.5f));
        {
            float p = t[2];                       // tap 18
            __stcs(op + W, fmaf(fminf(S[1], p), 0.5f, 0.5f));
            #pragma unroll
            for (int o = 2; o <= 15; ++o) {       // taps 19..32 = t[3..16]
                p = fminf(p, t[o + 1]);
                __stcs(op + (long)o * W, fmaf(fminf(S[o], p), 0.5f, 0.5f));
            }
        }

        // chunk B: output rows 16..31, taps 16..48
        op += 16 * W;
        {
            float s = t[17 - 0];                  // placeholder; real init below
            s = cp[33 * W];                       // tap 33
            #pragma unroll
            for (int i = 16; i >= 0; --i) {       // taps 32..16 = t[16..0]
                s = fminf(s, t[i]);
                if (i <= 15) S[i] = s;            // S[o] = min(taps 16+o .. 33)
            }
        }
        __stcs(op, fmaf(S[0], 0.5f, 0.5f));
        {
            float p = cp[34 * W];                 // tap 34
            __stcs(op + W, fmaf(fminf(S[1], p), 0.5f, 0.5f));
            #pragma unroll
            for (int o = 2; o <= 15; ++o) {       // taps 35..48
                p = fminf(p, cp[(o + 33) * W]);
                __stcs(op + (long)o * W, fmaf(fminf(S[o], p), 0.5f, 0.5f));
            }
        }
    }
}

extern "C" void kernel_launch(void* const* d_in, const int* in_sizes, int n_in,
                              void* d_out, int out_size) {
    const float* x = (const float*)d_in[0];
    float* out = (float*)d_out;

    // Idempotent host-side attribute set; not part of graph capture.
    cudaFuncSetAttribute(erode18_kernel,
                         cudaFuncAttributeMaxDynamicSharedMemorySize, SMEM_BYTES);

    dim3 grid(H / TY, 96);   // 8 x 96 = 768 blocks
    erode18_kernel<<<grid, NTHREADS, SMEM_BYTES>>>(x, out);
}

// round 6
// speedup vs baseline: 1.0396x; 1.0396x over previous
#include <cuda_runtime.h>
#include <cuda_bf16.h>

// Erosion (min filter) k=18, SAME (pad_lo=8, pad_hi=9), on y = x*0.5+0.5.
// NCHW (32,3,512,512) fp32 = 96 planes of 512x512.
//
// R4 structure + ring-buffer smem for 3 blocks/SM:
//  Phase A: warp-per-row horizontal min-18 via 10 wrap-shuffles per 128-col
//    round (coalesced LDG.128), results -> smem ring (33 rows of 512).
//  Phase B: thread-per-column vertical min-18 van Herk, two 16-row chunks;
//    ring refilled (16 rows) between chunks. Coalesced STG.32.
//  smem 67.6KB -> 3 blocks/SM (vs R4's 100KB/2): occ 47% -> ~68%.

#define W 512
#define H 512
#define TY 32
#define RING 33                    // ring rows held in smem
#define NTHREADS 512
#define SMEM_BYTES (RING * W * 4)  // 67,584 B

// Horizontal min-18 for one image row -> dst (512 floats), warp-collective.
// Window [-8,+9]; out-of-image cols/rows are +inf.
__device__ __forceinline__ void hrow_min18(const float* __restrict__ rowp_f,
                                           bool inb, float* __restrict__ dst,
                                           int lane) {
    const float INF = __int_as_float(0x7f800000);
    const unsigned FULL = 0xFFFFFFFFu;
    const float4* rowp = (const float4*)rowp_f;

    float4 v = inb ? __ldg(rowp + lane) : make_float4(INF, INF, INF, INF);
    float pS0 = INF, pS1 = INF, pS2 = INF, pS3 = INF, pF = INF;
    float4* orow = (float4*)dst;

    #pragma unroll
    for (int j = 0; j < 4; ++j) {
        float4 vn = (j < 3 && inb) ? __ldg(rowp + 32 * (j + 1) + lane)
                                   : make_float4(INF, INF, INF, INF);
        float P1 = fminf(v.x, v.y);
        float P2 = fminf(P1, v.z);
        float F  = fminf(P2, v.w);
        float S2 = fminf(v.z, v.w);
        float S1 = fminf(v.y, S2);
        float Pn1 = fminf(vn.x, vn.y);
        float Pn2 = fminf(Pn1, vn.z);
        float Fn  = fminf(Pn2, vn.w);

        // src = lane-2 (wrap); wrap sources 30,31 export prev-round values
        float eS0 = (lane >= 30) ? pS0 : F;
        float eS1 = (lane >= 30) ? pS1 : S1;
        float eS2 = (lane >= 30) ? pS2 : S2;
        float eS3 = (lane >= 30) ? pS3 : v.w;
        float u0 = __shfl_sync(FULL, eS0, (lane + 30) & 31);
        float u1 = __shfl_sync(FULL, eS1, (lane + 30) & 31);
        float u2 = __shfl_sync(FULL, eS2, (lane + 30) & 31);
        float u3 = __shfl_sync(FULL, eS3, (lane + 30) & 31);
        float eFu = (lane == 31) ? pF : F;
        float fu = __shfl_sync(FULL, eFu, (lane + 31) & 31);
        float eFd = (lane == 0) ? Fn : F;
        float fd = __shfl_sync(FULL, eFd, (lane + 1) & 31);
        float eP1 = (lane <= 1) ? Pn1 : P1;
        float eP2 = (lane <= 1) ? Pn2 : P2;
        float eP3 = (lane <= 1) ? Fn  : F;
        float d1 = __shfl_sync(FULL, eP1, (lane + 2) & 31);
        float d2 = __shfl_sync(FULL, eP2, (lane + 2) & 31);
        float d3 = __shfl_sync(FULL, eP3, (lane + 2) & 31);
        float evx = (lane <= 2) ? vn.x : v.x;
        float dx = __shfl_sync(FULL, evx, (lane + 3) & 31);

        float core = fminf(fminf(fu, F), fd);
        float4 ov;
        ov.x = fminf(fminf(u0, core), d1);
        ov.y = fminf(fminf(u1, core), d2);
        ov.z = fminf(fminf(u2, core), d3);
        ov.w = fminf(fminf(u3, core), fminf(d3, dx));
        orow[32 * j + lane] = ov;

        pS0 = F; pS1 = S1; pS2 = S2; pS3 = v.w; pF = F;
        v = vn;
    }
}

__global__ __launch_bounds__(NTHREADS, 3)
void erode18_kernel(const float* __restrict__ x, float* __restrict__ out) {
    extern __shared__ float s_h[];  // ring: [RING][W]

    const int tid  = threadIdx.x;
    const int lane = tid & 31;
    const int warp = tid >> 5;          // 0..15
    const int rowBase = blockIdx.x * TY;
    const long plane = (long)blockIdx.y * (W * H);

    // ---- Phase A: h-rows 0..32 (global rows rowBase-8 .. rowBase+24) ----
    for (int r = warp; r < RING; r += 16) {
        const int gr = rowBase - 8 + r;
        hrow_min18(x + plane + (long)gr * W,
                   (unsigned)gr < (unsigned)H, s_h + r * W, lane);
    }
    __syncthreads();

    // ---- Phase B chunk A: outputs rows rowBase+0..15, taps slots 0..32 ----
    {
        const float* cp = s_h + tid;
        float* op = out + plane + (long)rowBase * W + tid;
        float S[16];
        {
            float s = cp[17 * W];
            #pragma unroll
            for (int i = 16; i >= 0; --i) {
                s = fminf(s, cp[i * W]);
                if (i <= 15) S[i] = s;
            }
        }
        op[0] = fmaf(S[0], 0.5f, 0.5f);
        {
            float p = cp[18 * W];
            op[W] = fmaf(fminf(S[1], p), 0.5f, 0.5f);
            #pragma unroll
            for (int o = 2; o <= 15; ++o) {
                p = fminf(p, cp[(o + 17) * W]);
                op[(long)o * W] = fmaf(fminf(S[o], p), 0.5f, 0.5f);
            }
        }
    }
    __syncthreads();

    // ---- Phase A2: h-rows 33..48 -> dead slots 0..15 (one row per warp) ----
    {
        const int gr = rowBase + 25 + warp;       // global row of h-row 33+warp
        hrow_min18(x + plane + (long)gr * W,
                   (unsigned)gr < (unsigned)H, s_h + warp * W, lane);
    }
    __syncthreads();

    // ---- Phase B chunk B: outputs rows rowBase+16..31 ----
    // taps = h-rows 16+o .. 33+o ; slots: rows16..32 -> 16..32, row33+k -> k
    {
        const float* cp = s_h + tid;
        float* op = out + plane + (long)(rowBase + 16) * W + tid;
        float S[16];
        {
            float s = cp[0];                      // h-row 33 (slot 0)
            #pragma unroll
            for (int i = 32; i >= 16; --i) {      // h-rows 32..16
                s = fminf(s, cp[i * W]);
                if (i <= 31) S[i - 16] = s;       // S[o] = min(h-rows 16+o..33)
            }
        }
        op[0] = fmaf(S[0], 0.5f, 0.5f);
        {
            float p = cp[1 * W];                  // h-row 34 (slot 1)
            op[W] = fmaf(fminf(S[1], p), 0.5f, 0.5f);
            #pragma unroll
            for (int o = 2; o <= 15; ++o) {
                p = fminf(p, cp[o * W]);          // h-row 33+o (slot o)
                op[(long)o * W] = fmaf(fminf(S[o], p), 0.5f, 0.5f);
            }
        }
    }
}

extern "C" void kernel_launch(void* const* d_in, const int* in_sizes, int n_in,
                              void* d_out, int out_size) {
    const float* x = (const float*)d_in[0];
    float* out = (float*)d_out;

    // Idempotent host-side attribute set; not part of graph capture.
    cudaFuncSetAttribute(erode18_kernel,
                         cudaFuncAttributeMaxDynamicSharedMemorySize, SMEM_BYTES);

    dim3 grid(H / TY, 96);   // 16 x 96 = 1536 blocks
    erode18_kernel<<<grid, NTHREADS, SMEM_BYTES>>>(x, out);
}

// round 7
// speedup vs baseline: 1.0770x; 1.0359x over previous
#include <cuda_runtime.h>
#include <cuda_bf16.h>

// Erosion (min filter) k=18, SAME (pad_lo=8, pad_hi=9), on y = x*0.5+0.5.
// NCHW (32,3,512,512) fp32 = 96 planes of 512x512.
//
// Horizontal-first fused separable min filter (R4 skeleton):
//  Phase A: warp-per-row, lane owns 4 contiguous cols (float4): coalesced
//    LDG.128 + STS.128; 18-wide window from per-lane prefix/suffix mins via
//    10 wrap-shuffles per 128-col round. 49 h-min rows -> smem.
//  Phase B: thread-per-column, EXACT-ONCE tap reads: 3-segment van Herk
//    aligned at taps 18/36 -> 49 scalar LDS per 32 outputs (was 66).
//    Emission interleaved with the scans; coalesced STG.32, pointer-walk
//    addressing. One barrier. 0.5x+0.5 applied at the store.

#define W 512
#define H 512
#define TY 32
#define HROWS (TY + 17)            // 49 horizontal-result rows
#define NTHREADS 512
#define SMEM_BYTES (HROWS * W * 4) // 100,352 B

__global__ __launch_bounds__(NTHREADS, 2)
void erode18_kernel(const float* __restrict__ x, float* __restrict__ out) {
    extern __shared__ float s_h[];  // [HROWS][W]

    const int tid  = threadIdx.x;
    const int lane = tid & 31;
    const int warp = tid >> 5;
    const int rowBase = blockIdx.x * TY;
    const long plane = (long)blockIdx.y * (W * H);
    const float INF = __int_as_float(0x7f800000);
    const unsigned FULL = 0xFFFFFFFFu;

    // ================= Phase A: horizontal min-18, warp-per-row =================
    for (int r = warp; r < HROWS; r += 16) {
        const int gr = rowBase - 8 + r;
        const bool inb = (unsigned)gr < (unsigned)H;
        const float4* rowp = (const float4*)(x + plane + (long)gr * W);

        float4 v = inb ? __ldg(rowp + lane)
                       : make_float4(INF, INF, INF, INF);
        float pS0 = INF, pS1 = INF, pS2 = INF, pS3 = INF, pF = INF;
        float4* orow = (float4*)(s_h + r * W);

        #pragma unroll
        for (int j = 0; j < 4; ++j) {
            float4 vn = (j < 3 && inb) ? __ldg(rowp + 32 * (j + 1) + lane)
                                       : make_float4(INF, INF, INF, INF);
            float P1 = fminf(v.x, v.y);
            float P2 = fminf(P1, v.z);
            float F  = fminf(P2, v.w);
            float S2 = fminf(v.z, v.w);
            float S1 = fminf(v.y, S2);
            float Pn1 = fminf(vn.x, vn.y);
            float Pn2 = fminf(Pn1, vn.z);
            float Fn  = fminf(Pn2, vn.w);

            // src = lane-2 (wrap); wrap sources 30,31 export prev-round values
            float eS0 = (lane >= 30) ? pS0 : F;
            float eS1 = (lane >= 30) ? pS1 : S1;
            float eS2 = (lane >= 30) ? pS2 : S2;
            float eS3 = (lane >= 30) ? pS3 : v.w;
            float u0 = __shfl_sync(FULL, eS0, (lane + 30) & 31);
            float u1 = __shfl_sync(FULL, eS1, (lane + 30) & 31);
            float u2 = __shfl_sync(FULL, eS2, (lane + 30) & 31);
            float u3 = __shfl_sync(FULL, eS3, (lane + 30) & 31);
            float eFu = (lane == 31) ? pF : F;
            float fu = __shfl_sync(FULL, eFu, (lane + 31) & 31);
            float eFd = (lane == 0) ? Fn : F;
            float fd = __shfl_sync(FULL, eFd, (lane + 1) & 31);
            float eP1 = (lane <= 1) ? Pn1 : P1;
            float eP2 = (lane <= 1) ? Pn2 : P2;
            float eP3 = (lane <= 1) ? Fn  : F;
            float d1 = __shfl_sync(FULL, eP1, (lane + 2) & 31);
            float d2 = __shfl_sync(FULL, eP2, (lane + 2) & 31);
            float d3 = __shfl_sync(FULL, eP3, (lane + 2) & 31);
            float evx = (lane <= 2) ? vn.x : v.x;
            float dx = __shfl_sync(FULL, evx, (lane + 3) & 31);

            float core = fminf(fminf(fu, F), fd);
            float4 ov;
            ov.x = fminf(fminf(u0, core), d1);
            ov.y = fminf(fminf(u1, core), d2);
            ov.z = fminf(fminf(u2, core), d3);
            ov.w = fminf(fminf(u3, core), fminf(d3, dx));
            orow[32 * j + lane] = ov;

            pS0 = F; pS1 = S1; pS2 = S2; pS3 = v.w; pF = F;
            v = vn;
        }
    }
    __syncthreads();

    // ===== Phase B: vertical min-18, thread-per-column, exact-once taps =====
    // taps t[i] = s_h[i*W + col], i = 0..48; out[o] = min(t[o..o+17]), o=0..31
    {
        const float* cp = s_h + tid;
        float* op = out + plane + (long)rowBase * W + tid;

        // --- segment 1: suffix over taps 0..17 -> S0[i] = min(t[i..17]) ---
        float S0[18];
        {
            float s = cp[17 * W];
            S0[17] = s;
            #pragma unroll
            for (int i = 16; i >= 0; --i) {
                s = fminf(s, cp[i * W]);
                S0[i] = s;
            }
        }
        *op = fmaf(S0[0], 0.5f, 0.5f);   // out[0] = min(t[0..17])
        op += W;

        // --- segment 2: read taps 18..35 into t1, prefix-emit out[1..18] ---
        float t1[18];
        {
            float p = INF;
            #pragma unroll
            for (int i = 0; i <= 17; ++i) {     // tap 18+i
                float v = cp[(18 + i) * W];
                t1[i] = v;
                p = fminf(p, v);                // p = min(t[18..18+i])
                // out[i+1] = min(S0[i+1], p) for i<=16 ; out[18] = p at i=17
                float o = (i <= 16) ? fminf(S0[i + 1], p) : p;
                *op = fmaf(o, 0.5f, 0.5f);
                op += W;
            }
        }

        // --- suffix over t1 in place: S1[i] = min(t1[i..17]) ---
        #pragma unroll
        for (int i = 16; i >= 0; --i) t1[i] = fminf(t1[i], t1[i + 1]);

        // --- segment 3: taps 36..48, prefix-emit out[19..31] ---
        {
            float q = INF;
            #pragma unroll
            for (int i = 0; i <= 12; ++i) {     // tap 36+i
                q = fminf(q, cp[(36 + i) * W]); // q = min(t[36..36+i])
                *op = fmaf(fminf(t1[i + 1], q), 0.5f, 0.5f);  // out[19+i]
                op += W;
            }
        }
    }
}

extern "C" void kernel_launch(void* const* d_in, const int* in_sizes, int n_in,
                              void* d_out, int out_size) {
    const float* x = (const float*)d_in[0];
    float* out = (float*)d_out;

    // Idempotent host-side attribute set; not part of graph capture.
    cudaFuncSetAttribute(erode18_kernel,
                         cudaFuncAttributeMaxDynamicSharedMemorySize, SMEM_BYTES);

    dim3 grid(H / TY, 96);   // 16 x 96 = 1536 blocks
    erode18_kernel<<<grid, NTHREADS, SMEM_BYTES>>>(x, out);
}

// round 8
// speedup vs baseline: 1.2577x; 1.1678x over previous
#include <cuda_runtime.h>
#include <cuda_bf16.h>

// Erosion (min filter) k=18, SAME (pad_lo=8, pad_hi=9), on y = x*0.5+0.5.
// NCHW (32,3,512,512) fp32 = 96 planes of 512x512.
//
// Vertical-FIRST fused separable min filter (halo on the cheap pass):
//  Phase V: thread-per-column. 49 coalesced LDG.32 (1 wf each), exact-once
//    3-segment van Herk in registers, 32 vmin rows -> smem (coalesced STS.32).
//  Phase H: warp-per-row on only 32 rows (no halo!): lane owns 4 contiguous
//    cols, conflict-free LDS.128, 18-wide window via 10 wrap-shuffles per
//    128-col round, fused 0.5x+0.5, coalesced STG.128.
//  smem 64KB -> 3 blocks/SM. One barrier.

#define W 512
#define H 512
#define TY 32
#define NTHREADS 512
#define SMEM_BYTES (TY * W * 4)    // 65,536 B

__global__ __launch_bounds__(NTHREADS, 3)
void erode18_kernel(const float* __restrict__ x, float* __restrict__ out) {
    extern __shared__ float s_v[];  // [TY][W] vertical-min tile

    const int tid  = threadIdx.x;
    const int lane = tid & 31;
    const int warp = tid >> 5;
    const int rowBase = blockIdx.x * TY;
    const long plane = (long)blockIdx.y * (W * H);
    const float INF = __int_as_float(0x7f800000);
    const unsigned FULL = 0xFFFFFFFFu;

    // ========== Phase V: vertical min-18, thread-per-column, exact-once ==========
    // taps t[i] = x[rowBase-8+i][c], i=0..48 (+inf OOB); vmin[o]=min(t[o..o+17])
    {
        const int c = tid;
        const float* gp = x + plane + c;
        const int g0 = rowBase - 8;

        // segment 1: suffix over taps 0..17 -> S0[i] = min(t[i..17])
        float S0[18];
        {
            int gr = g0 + 17;
            float s = ((unsigned)gr < (unsigned)H) ? gp[(long)gr * W] : INF;
            S0[17] = s;
            #pragma unroll
            for (int i = 16; i >= 0; --i) {
                gr = g0 + i;
                float v = ((unsigned)gr < (unsigned)H) ? gp[(long)gr * W] : INF;
                s = fminf(s, v);
                S0[i] = s;
            }
        }
        s_v[0 * W + c] = S0[0];

        // segment 2: taps 18..35 -> t1, prefix-emit vmin[1..18]
        float t1[18];
        {
            float p = INF;
            #pragma unroll
            for (int i = 0; i <= 17; ++i) {
                int gr = g0 + 18 + i;
                float v = ((unsigned)gr < (unsigned)H) ? gp[(long)gr * W] : INF;
                t1[i] = v;
                p = fminf(p, v);
                float o = (i <= 16) ? fminf(S0[i + 1], p) : p;
                s_v[(i + 1) * W + c] = o;
            }
        }

        // suffix over t1 in place: t1[i] = min(t1[i..17])
        #pragma unroll
        for (int i = 16; i >= 0; --i) t1[i] = fminf(t1[i], t1[i + 1]);

        // segment 3: taps 36..48, prefix-emit vmin[19..31]
        {
            float q = INF;
            #pragma unroll
            for (int i = 0; i <= 12; ++i) {
                int gr = g0 + 36 + i;
                float v = ((unsigned)gr < (unsigned)H) ? gp[(long)gr * W] : INF;
                q = fminf(q, v);
                s_v[(19 + i) * W + c] = fminf(t1[i + 1], q);
            }
        }
    }
    __syncthreads();

    // ========== Phase H: horizontal min-18, warp-per-row (32 rows) ==========
    #pragma unroll
    for (int rr = 0; rr < 2; ++rr) {
        const int r = warp + rr * 16;
        const float4* srow = (const float4*)(s_v + r * W);
        float4* orow = (float4*)(out + plane + (long)(rowBase + r) * W);

        float4 v = srow[lane];
        float pS0 = INF, pS1 = INF, pS2 = INF, pS3 = INF, pF = INF;

        #pragma unroll
        for (int j = 0; j < 4; ++j) {
            float4 vn = (j < 3) ? srow[32 * (j + 1) + lane]
                                : make_float4(INF, INF, INF, INF);
            float P1 = fminf(v.x, v.y);
            float P2 = fminf(P1, v.z);
            float F  = fminf(P2, v.w);
            float S2 = fminf(v.z, v.w);
            float S1 = fminf(v.y, S2);
            float Pn1 = fminf(vn.x, vn.y);
            float Pn2 = fminf(Pn1, vn.z);
            float Fn  = fminf(Pn2, vn.w);

            // src = lane-2 (wrap); wrap sources 30,31 export prev-round values
            float eS0 = (lane >= 30) ? pS0 : F;
            float eS1 = (lane >= 30) ? pS1 : S1;
            float eS2 = (lane >= 30) ? pS2 : S2;
            float eS3 = (lane >= 30) ? pS3 : v.w;
            float u0 = __shfl_sync(FULL, eS0, (lane + 30) & 31);
            float u1 = __shfl_sync(FULL, eS1, (lane + 30) & 31);
            float u2 = __shfl_sync(FULL, eS2, (lane + 30) & 31);
            float u3 = __shfl_sync(FULL, eS3, (lane + 30) & 31);
            float eFu = (lane == 31) ? pF : F;
            float fu = __shfl_sync(FULL, eFu, (lane + 31) & 31);
            float eFd = (lane == 0) ? Fn : F;
            float fd = __shfl_sync(FULL, eFd, (lane + 1) & 31);
            float eP1 = (lane <= 1) ? Pn1 : P1;
            float eP2 = (lane <= 1) ? Pn2 : P2;
            float eP3 = (lane <= 1) ? Fn  : F;
            float d1 = __shfl_sync(FULL, eP1, (lane + 2) & 31);
            float d2 = __shfl_sync(FULL, eP2, (lane + 2) & 31);
            float d3 = __shfl_sync(FULL, eP3, (lane + 2) & 31);
            float evx = (lane <= 2) ? vn.x : v.x;
            float dx = __shfl_sync(FULL, evx, (lane + 3) & 31);

            float core = fminf(fminf(fu, F), fd);
            float4 ov;
            ov.x = fmaf(fminf(fminf(u0, core), d1), 0.5f, 0.5f);
            ov.y = fmaf(fminf(fminf(u1, core), d2), 0.5f, 0.5f);
            ov.z = fmaf(fminf(fminf(u2, core), d3), 0.5f, 0.5f);
            ov.w = fmaf(fminf(fminf(u3, core), fminf(d3, dx)), 0.5f, 0.5f);
            orow[32 * j + lane] = ov;

            pS0 = F; pS1 = S1; pS2 = S2; pS3 = v.w; pF = F;
            v = vn;
        }
    }
}

extern "C" void kernel_launch(void* const* d_in, const int* in_sizes, int n_in,
                              void* d_out, int out_size) {
    const float* x = (const float*)d_in[0];
    float* out = (float*)d_out;

    // Idempotent host-side attribute set; not part of graph capture.
    cudaFuncSetAttribute(erode18_kernel,
                         cudaFuncAttributeMaxDynamicSharedMemorySize, SMEM_BYTES);

    dim3 grid(H / TY, 96);   // 16 x 96 = 1536 blocks
    erode18_kernel<<<grid, NTHREADS, SMEM_BYTES>>>(x, out);
}

// round 9
// speedup vs baseline: 1.2965x; 1.0309x over previous
#include <cuda_runtime.h>
#include <cuda_bf16.h>

// Erosion (min filter) k=18, SAME (pad_lo=8, pad_hi=9), on y = x*0.5+0.5.
// NCHW (32,3,512,512) fp32 = 96 planes of 512x512.
//
// Vertical-FIRST fused separable min filter (R8 skeleton):
//  Phase V: thread-per-column. 49 coalesced LDG.32, exact-once 3-segment
//    van Herk in registers, 32 vmin rows -> smem. Interior blocks (14/16)
//    take an UNGUARDED pointer-walk path: no bounds ISETP/SEL per tap.
//  Phase H: warp-per-row on 32 rows: lane owns 4 contiguous cols,
//    conflict-free LDS.128, 18-wide window via 10 wrap-shuffles per 128-col
//    round, fused 0.5x+0.5, coalesced STG.128.
//  smem 64KB -> 3 blocks/SM. One barrier.

#define W 512
#define H 512
#define TY 32
#define NTHREADS 512
#define SMEM_BYTES (TY * W * 4)    // 65,536 B

// Vertical min-18 for one column, exact-once taps (49 loads), results to smem.
// GUARD=false: all tap rows known in-bounds (no predication at all).
template <bool GUARD>
__device__ __forceinline__ void vcol_min18(const float* __restrict__ gp,
                                           int g0, float* __restrict__ s_col) {
    const float INF = __int_as_float(0x7f800000);
    const float* p = gp + (long)g0 * W;   // tap 0 pointer (may be OOB if GUARD)

    // segment 1: suffix over taps 0..17 -> S0[i] = min(t[i..17])
    float S0[18];
    {
        float s;
        if (GUARD) {
            int gr = g0 + 17;
            s = ((unsigned)gr < (unsigned)H) ? p[17 * W] : INF;
        } else {
            s = p[17 * W];
        }
        S0[17] = s;
        #pragma unroll
        for (int i = 16; i >= 0; --i) {
            float v;
            if (GUARD) {
                int gr = g0 + i;
                v = ((unsigned)gr < (unsigned)H) ? p[i * W] : INF;
            } else {
                v = p[i * W];
            }
            s = fminf(s, v);
            S0[i] = s;
        }
    }
    s_col[0] = S0[0];

    // segment 2: taps 18..35 -> t1, prefix-emit vmin[1..18]
    float t1[18];
    {
        float pr = INF;
        #pragma unroll
        for (int i = 0; i <= 17; ++i) {
            float v;
            if (GUARD) {
                int gr = g0 + 18 + i;
                v = ((unsigned)gr < (unsigned)H) ? p[(18 + i) * W] : INF;
            } else {
                v = p[(18 + i) * W];
            }
            t1[i] = v;
            pr = fminf(pr, v);
            float o = (i <= 16) ? fminf(S0[i + 1], pr) : pr;
            s_col[(i + 1) * W] = o;
        }
    }

    // suffix over t1 in place: t1[i] = min(t1[i..17])
    #pragma unroll
    for (int i = 16; i >= 0; --i) t1[i] = fminf(t1[i], t1[i + 1]);

    // segment 3: taps 36..48, prefix-emit vmin[19..31]
    {
        float q = INF;
        #pragma unroll
        for (int i = 0; i <= 12; ++i) {
            float v;
            if (GUARD) {
                int gr = g0 + 36 + i;
                v = ((unsigned)gr < (unsigned)H) ? p[(36 + i) * W] : INF;
            } else {
                v = p[(36 + i) * W];
            }
            q = fminf(q, v);
            s_col[(19 + i) * W] = fminf(t1[i + 1], q);
        }
    }
}

__global__ __launch_bounds__(NTHREADS, 3)
void erode18_kernel(const float* __restrict__ x, float* __restrict__ out) {
    extern __shared__ float s_v[];  // [TY][W] vertical-min tile

    const int tid  = threadIdx.x;
    const int lane = tid & 31;
    const int warp = tid >> 5;
    const int rowBase = blockIdx.x * TY;
    const long plane = (long)blockIdx.y * (W * H);
    const float INF = __int_as_float(0x7f800000);
    const unsigned FULL = 0xFFFFFFFFu;

    // ========== Phase V: vertical min-18, thread-per-column, exact-once ==========
    {
        const float* gp = x + plane + tid;
        const int g0 = rowBase - 8;
        // interior: tap rows g0..g0+48 all inside [0, H)
        if (g0 >= 0 && g0 + 48 < H)
            vcol_min18<false>(gp, g0, s_v + tid);
        else
            vcol_min18<true>(gp, g0, s_v + tid);
    }
    __syncthreads();

    // ========== Phase H: horizontal min-18, warp-per-row (32 rows) ==========
    #pragma unroll
    for (int rr = 0; rr < 2; ++rr) {
        const int r = warp + rr * 16;
        const float4* srow = (const float4*)(s_v + r * W);
        float4* orow = (float4*)(out + plane + (long)(rowBase + r) * W);

        float4 v = srow[lane];
        float pS1 = INF, pS2 = INF, pS3 = INF, pF = INF;

        #pragma unroll
        for (int j = 0; j < 4; ++j) {
            float4 vn = (j < 3) ? srow[32 * (j + 1) + lane]
                                : make_float4(INF, INF, INF, INF);
            float P1 = fminf(v.x, v.y);
            float P2 = fminf(P1, v.z);
            float F  = fminf(P2, v.w);
            float S2 = fminf(v.z, v.w);
            float S1 = fminf(v.y, S2);
            float Pn1 = fminf(vn.x, vn.y);
            float Pn2 = fminf(Pn1, vn.z);
            float Fn  = fminf(Pn2, vn.w);

            // src = lane-2 (wrap); wrap sources 30,31 export prev-round values
            float eS0 = (lane >= 30) ? pF  : F;    // pS0 == pF
            float eS1 = (lane >= 30) ? pS1 : S1;
            float eS2 = (lane >= 30) ? pS2 : S2;
            float eS3 = (lane >= 30) ? pS3 : v.w;
            float u0 = __shfl_sync(FULL, eS0, (lane + 30) & 31);
            float u1 = __shfl_sync(FULL, eS1, (lane + 30) & 31);
            float u2 = __shfl_sync(FULL, eS2, (lane + 30) & 31);
            float u3 = __shfl_sync(FULL, eS3, (lane + 30) & 31);
            float eFu = (lane == 31) ? pF : F;
            float fu = __shfl_sync(FULL, eFu, (lane + 31) & 31);
            float eFd = (lane == 0) ? Fn : F;
            float fd = __shfl_sync(FULL, eFd, (lane + 1) & 31);
            float eP1 = (lane <= 1) ? Pn1 : P1;
            float eP2 = (lane <= 1) ? Pn2 : P2;
            float eP3 = (lane <= 1) ? Fn  : F;
            float d1 = __shfl_sync(FULL, eP1, (lane + 2) & 31);
            float d2 = __shfl_sync(FULL, eP2, (lane + 2) & 31);
            float d3 = __shfl_sync(FULL, eP3, (lane + 2) & 31);
            float evx = (lane <= 2) ? vn.x : v.x;
            float dx = __shfl_sync(FULL, evx, (lane + 3) & 31);

            float core = fminf(fminf(fu, F), fd);
            float4 ov;
            ov.x = fmaf(fminf(fminf(u0, core), d1), 0.5f, 0.5f);
            ov.y = fmaf(fminf(fminf(u1, core), d2), 0.5f, 0.5f);
            ov.z = fmaf(fminf(fminf(u2, core), d3), 0.5f, 0.5f);
            ov.w = fmaf(fminf(fminf(u3, core), fminf(d3, dx)), 0.5f, 0.5f);
            orow[32 * j + lane] = ov;

            pS1 = S1; pS2 = S2; pS3 = v.w; pF = F;
            v = vn;
        }
    }
}

extern "C" void kernel_launch(void* const* d_in, const int* in_sizes, int n_in,
                              void* d_out, int out_size) {
    const float* x = (const float*)d_in[0];
    float* out = (float*)d_out;

    // Idempotent host-side attribute set; not part of graph capture.
    cudaFuncSetAttribute(erode18_kernel,
                         cudaFuncAttributeMaxDynamicSharedMemorySize, SMEM_BYTES);

    dim3 grid(H / TY, 96);   // 16 x 96 = 1536 blocks
    erode18_kernel<<<grid, NTHREADS, SMEM_BYTES>>>(x, out);
}